// round 14
// baseline (speedup 1.0000x reference)
#include <cuda_runtime.h>
#include <cstdint>

// EvalBspPrimeTF: derivative of Bernstein basis, order 16, 4M points -> [4M,17] f32.
// Telescoping form: U_m = 16*C(15,m)*y^m*(1-y)^(15-m), m=0..15
//   out[0] = -U_0;  out[m] = U_{m-1} - U_m (1<=m<=15);  out[16] = U_15
// Reference NaN->0: at y==0, out[0]=out[1]=0; at y==1, out[15]=out[16]=0.
//
// R14: coarsest tile point — TPB=512, one 34816B TMA bulk store per CTA,
// 7813 CTAs. Per-CTA fixed costs (launch latency, barrier, tail drain)
// amortized over 2x points vs TPB=256; half the TMA commit transactions.

#define TPB   512
#define NCOL  17
#define TILE_WORDS (TPB * NCOL)          // 8704 floats
#define TILE_BYTES (TILE_WORDS * 4)      // 34816 B, multiple of 16

__device__ __forceinline__ void compute_point(float y, float* __restrict__ o)
{
    // 16*C(15,m)
    const float K[16] = {
        16.f, 240.f, 1680.f, 7280.f, 21840.f, 48048.f, 80080.f, 102960.f,
        102960.f, 80080.f, 48048.f, 21840.f, 7280.f, 1680.f, 240.f, 16.f
    };
    float q = 1.0f - y;

    float yp[16], qp[16];
    yp[0] = 1.0f; qp[0] = 1.0f;
#pragma unroll
    for (int k = 1; k < 16; ++k) {
        yp[k] = yp[k - 1] * y;
        qp[k] = qp[k - 1] * q;
    }

    float U[16];
#pragma unroll
    for (int m = 0; m < 16; ++m)
        U[m] = K[m] * yp[m] * qp[15 - m];

    o[0] = -U[0];
#pragma unroll
    for (int m = 1; m < 16; ++m)
        o[m] = U[m - 1] - U[m];
    o[16] = U[15];

    if (y == 0.0f) { o[0]  = 0.0f; o[1]  = 0.0f; }
    if (y == 1.0f) { o[15] = 0.0f; o[16] = 0.0f; }
}

__global__ __launch_bounds__(TPB)
void evalbspprime_kernel(const float* __restrict__ x,
                         float* __restrict__ out,
                         int n)
{
    __shared__ __align__(128) float s[TILE_WORDS];   // 34816 B

    const int tid  = threadIdx.x;
    const int base = blockIdx.x * TPB;
    const int idx  = base + tid;

    float y = (idx < n) ? x[idx] : 0.5f;
    float o[NCOL];
    compute_point(y, o);

    // stride-17 words per thread: 17 coprime to 32 banks -> conflict-free
#pragma unroll
    for (int m = 0; m < NCOL; ++m)
        s[tid * NCOL + m] = o[m];

    __syncthreads();

    if (base + TPB <= n) {
        if (tid == 0) {
            asm volatile("fence.proxy.async.shared::cta;" ::: "memory");
            uint32_t saddr = (uint32_t)__cvta_generic_to_shared(s);
            const float* g = out + (long long)base * NCOL;
            asm volatile(
                "cp.async.bulk.global.shared::cta.bulk_group [%0], [%1], %2;"
                :: "l"(g), "r"(saddr), "n"(TILE_BYTES) : "memory");
            asm volatile("cp.async.bulk.commit_group;" ::: "memory");
            // drain before CTA exit (smem dealloc safety)
            asm volatile("cp.async.bulk.wait_group.read 0;" ::: "memory");
        }
    } else {
        // tail (absent for n = 4,000,000): coalesced scalar fallback
        const long long obase = (long long)base * NCOL;
        const int rem = (n - base) * NCOL;
        for (int i = tid; i < rem; i += TPB)
            out[obase + i] = s[i];
    }
}

extern "C" void kernel_launch(void* const* d_in, const int* in_sizes, int n_in,
                              void* d_out, int out_size)
{
    const float* x = (const float*)d_in[0];
    float* out = (float*)d_out;
    const int n = in_sizes[0];          // 4,000,000
    const int blocks = (n + TPB - 1) / TPB;   // 7813
    evalbspprime_kernel<<<blocks, TPB>>>(x, out, n);
}